// round 15
// baseline (speedup 1.0000x reference)
#include <cuda_runtime.h>
#include <cstdint>

#define B   8
#define N   4096
#define F   128
#define GS  1024
#define TPB 256

// Final top-k indices (jax order) + replay-safe handshake flags (zero-init)
__device__ int g_idx[B * GS];
__device__ int g_done[B];
__device__ int g_exit[B];

__device__ __forceinline__ unsigned int monot(float v) {
    unsigned int u = __float_as_uint(v);
    return (u & 0x80000000u) ? ~u : (u | 0x80000000u); // bigger float -> bigger uint
}

// Shared memory union: gather uses row[]; select uses sel.*  (16 KB total)
union SmemU {
    float row[N];                               // 16 KB (gather)
    struct {
        unsigned long long stage[GS];           // 8 KB sorted keys
        unsigned int hist[256];                 // 1 KB
        unsigned int bin, above, cnt;
    } sel;
};

// scan_hist: warp 0 finds bin containing the `need`-th largest + count above.
__device__ __forceinline__ void scan_hist_s(const unsigned int* hist, unsigned int need,
                                            unsigned int* o_bin, unsigned int* o_above)
{
    const int tid = threadIdx.x;
    if (tid < 32) {
        unsigned int sum = 0;
        #pragma unroll
        for (int j = 0; j < 8; ++j) sum += hist[tid * 8 + j];
        unsigned int acc = sum;
        #pragma unroll
        for (int off = 1; off < 32; off <<= 1) {
            unsigned int t = __shfl_down_sync(0xFFFFFFFFu, acc, off);
            if (tid + off < 32) acc += t;
        }
        unsigned int running = acc - sum;      // strictly above my 8-bin group
        #pragma unroll
        for (int j = 7; j >= 0; --j) {
            unsigned int c = hist[tid * 8 + j];
            if (running < need && need <= running + c) {
                *o_bin = (unsigned int)(tid * 8 + j);
                *o_above = running;
            }
            running += c;
        }
    }
}

// ---------------------------------------------------------------------------
// Fused kernel. bids 0..B-1: per-batch select+sort (keys in registers).
// bids B..B+B*GS-1: one output row each (R13-proven gather), gated on g_done.
// composite = (u << 12) | (4095 - i): larger == earlier in jax order; unique.
// ---------------------------------------------------------------------------
__global__ __launch_bounds__(TPB) void fused_kernel(const float* __restrict__ A,
                                                    const float* __restrict__ x,
                                                    float* __restrict__ out)
{
    __shared__ SmemU sm;
    const int tid = threadIdx.x;

    if (blockIdx.x < B) {
        // ================= SELECT + SORT (batch b) =================
        const int b = blockIdx.x;
        auto& S = sm.sel;

        S.hist[tid] = 0;
        if (tid == 0) S.cnt = 0;
        __syncthreads();

        // 16 keys per thread, registers only (MLP-16 strided loads)
        unsigned long long comp[16];
        #pragma unroll
        for (int l = 0; l < 16; ++l) {
            const int i = l * TPB + tid;
            unsigned int u = monot(__ldcs(&x[((size_t)b * N + i) * F + (F - 1)]));
            comp[l] = ((unsigned long long)u << 12) | (unsigned int)(N - 1 - i);
        }
        #pragma unroll
        for (int l = 0; l < 16; ++l)
            atomicAdd(&S.hist[(unsigned int)(comp[l] >> 36)], 1u);
        __syncthreads();

        scan_hist_s(S.hist, GS, &S.bin, &S.above);
        __syncthreads();
        unsigned int need = GS - S.above;
        unsigned long long prefix = (unsigned long long)S.bin << 36;
        unsigned long long pmask  = 0xFFull << 36;
        __syncthreads();

        // 5 refinement passes over register-resident keys
        #pragma unroll
        for (int pass = 0; pass < 5; ++pass) {
            const int          shift = (pass < 4) ? (28 - 8 * pass) : 0;
            const unsigned int dmask = (pass < 4) ? 0xFFu : 0xFu;

            S.hist[tid] = 0;
            __syncthreads();
            #pragma unroll
            for (int l = 0; l < 16; ++l) {
                if ((comp[l] & pmask) == prefix)
                    atomicAdd(&S.hist[(unsigned int)(comp[l] >> shift) & dmask], 1u);
            }
            __syncthreads();
            scan_hist_s(S.hist, need, &S.bin, &S.above);
            __syncthreads();
            prefix |= ((unsigned long long)S.bin) << shift;
            pmask  |= ((unsigned long long)dmask) << shift;
            need   -= S.above;
            __syncthreads();
        }
        // Selected set: composite >= prefix (exactly GS keys, unique).

        #pragma unroll
        for (int l = 0; l < 16; ++l) {
            if (comp[l] >= prefix) {
                unsigned int p = atomicAdd(&S.cnt, 1u);
                S.stage[p] = comp[l];
            }
        }
        __syncthreads();

        // Bitonic sort DESC, 256 threads x 4 elements, smem stages
        for (int k = 2; k <= GS; k <<= 1) {
            for (int j = k >> 1; j > 0; j >>= 1) {
                #pragma unroll
                for (int l = 0; l < 4; ++l) {
                    const int t   = l * TPB + tid;
                    const int ixj = t ^ j;
                    if (ixj > t) {
                        unsigned long long a = S.stage[t];
                        unsigned long long c = S.stage[ixj];
                        const bool up = ((t & k) == 0);
                        if ((a < c) == up) { S.stage[t] = c; S.stage[ixj] = a; }
                    }
                }
                __syncthreads();
            }
        }

        #pragma unroll
        for (int l = 0; l < 4; ++l) {
            const int t = l * TPB + tid;
            g_idx[b * GS + t] = (N - 1) - (int)(S.stage[t] & 0xFFFull);
        }
        __threadfence();
        __syncthreads();
        if (tid == 0) atomicExch(&g_done[b], 1);   // release

    } else {
        // ================= GATHER (one output row) =================
        const int bi = blockIdx.x - B;
        const int b  = bi >> 10;
        const int i  = bi & (GS - 1);

        // Gate on select completion; re-arm flags for graph replay.
        if (tid == 0) {
            while (atomicAdd(&g_done[b], 0) == 0) __nanosleep(128);
            __threadfence();                       // acquire
            int old = atomicAdd(&g_exit[b], 1);
            if (old == GS - 1) {                   // last CTA of batch: reset
                atomicExch(&g_exit[b], 0);
                atomicExch(&g_done[b], 0);
            }
        }
        __syncthreads();

        const int* gi = g_idx + b * GS;
        const int ri  = __ldg(&gi[i]);

        // My four column indices (coalesced, L2-resident)
        const int ci0 = __ldg(&gi[tid]);
        const int ci1 = __ldg(&gi[tid + 256]);
        const int ci2 = __ldg(&gi[tid + 512]);
        const int ci3 = __ldg(&gi[tid + 768]);

        const float4* arow = (const float4*)(A + ((size_t)b * N + ri) * N);
        float4* rowv = (float4*)sm.row;
        rowv[tid]       = __ldcs(&arow[tid]);
        rowv[tid + 256] = __ldcs(&arow[tid + 256]);
        rowv[tid + 512] = __ldcs(&arow[tid + 512]);
        rowv[tid + 768] = __ldcs(&arow[tid + 768]);

        if (tid < F / 4) {
            const float4* xrow = (const float4*)(x + ((size_t)b * N + ri) * F);
            float4* xgrow = (float4*)(out + (size_t)B * GS * GS
                                          + ((size_t)b * GS + i) * F);
            xgrow[tid] = xrow[tid];
        }

        __syncthreads();

        float* orow = out + ((size_t)b * GS + i) * GS;
        orow[tid]       = sm.row[ci0];
        orow[tid + 256] = sm.row[ci1];
        orow[tid + 512] = sm.row[ci2];
        orow[tid + 768] = sm.row[ci3];
    }
}

// ---------------------------------------------------------------------------
extern "C" void kernel_launch(void* const* d_in, const int* in_sizes, int n_in,
                              void* d_out, int out_size)
{
    const float* A = (const float*)d_in[0];  // (8,4096,4096) f32
    const float* x = (const float*)d_in[1];  // (8,4096,128)  f32
    float* out = (float*)d_out;              // At2 (8,1024,1024) ++ xg (8,1024,128)

    fused_kernel<<<B + B * GS, TPB>>>(A, x, out);
}

// round 16
// speedup vs baseline: 2.0251x; 2.0251x over previous
#include <cuda_runtime.h>
#include <cstdint>

#define B  8
#define N  4096
#define F  128
#define GS 1024

// Scratch
__device__ unsigned long long g_sel[B * GS];  // selected composites, unordered
__device__ int                g_idx[B * GS];  // final top-k indices, jax order

__device__ __forceinline__ unsigned int monot(float v) {
    unsigned int u = __float_as_uint(v);
    return (u & 0x80000000u) ? ~u : (u | 0x80000000u); // bigger float -> bigger uint
}

// ---------------------------------------------------------------------------
// scan_hist: warp 0 finds bin containing the `need`-th largest + count above.
// ---------------------------------------------------------------------------
__device__ __forceinline__ void scan_hist(const unsigned int* hist, unsigned int need,
                                          unsigned int* s_bin, unsigned int* s_above)
{
    const int tid = threadIdx.x;
    if (tid < 32) {
        unsigned int sum = 0;
        #pragma unroll
        for (int j = 0; j < 8; ++j) sum += hist[tid * 8 + j];
        unsigned int acc = sum;
        #pragma unroll
        for (int off = 1; off < 32; off <<= 1) {
            unsigned int t = __shfl_down_sync(0xFFFFFFFFu, acc, off);
            if (tid + off < 32) acc += t;
        }
        unsigned int running = acc - sum;      // strictly above my 8-bin group
        #pragma unroll
        for (int j = 7; j >= 0; --j) {
            unsigned int c = hist[tid * 8 + j];
            if (running < need && need <= running + c) {
                *s_bin = (unsigned int)(tid * 8 + j);
                *s_above = running;
            }
            running += c;
        }
    }
}

// ---------------------------------------------------------------------------
// K1: per-batch select ONLY (no sort). 8 CTAs x 1024 thr.
//   strided extraction (4/thread) -> hist -> threshold-bin candidates ->
//   5 candidate-only radix passes -> exact cutoff -> unordered compact.
// composite = (u << 12) | (4095 - i): larger == earlier in jax order; unique.
// ---------------------------------------------------------------------------
__global__ __launch_bounds__(1024) void select_kernel(const float* __restrict__ x)
{
    __shared__ unsigned long long cand[N];      // 32 KB (worst-case threshold bin)
    __shared__ unsigned int hist[256];
    __shared__ unsigned int s_bin, s_above, s_m, s_cnt;

    const int b   = blockIdx.x;
    const int tid = threadIdx.x;

    if (tid < 256) hist[tid] = 0;
    if (tid == 0) { s_m = 0; s_cnt = 0; }
    __syncthreads();

    // Load 4 values per thread (MLP-4), build composites, histogram top-8 bits
    unsigned long long comp[4];
    #pragma unroll
    for (int l = 0; l < 4; ++l) {
        const int i = l * 1024 + tid;
        unsigned int u = monot(__ldcs(&x[((size_t)b * N + i) * F + (F - 1)]));
        comp[l] = ((unsigned long long)u << 12) | (unsigned int)(N - 1 - i);
    }
    #pragma unroll
    for (int l = 0; l < 4; ++l)
        atomicAdd(&hist[(unsigned int)(comp[l] >> 36)], 1u);
    __syncthreads();

    scan_hist(hist, GS, &s_bin, &s_above);
    __syncthreads();
    const unsigned int bin1 = s_bin;
    unsigned int need = GS - s_above;

    // Compact threshold-bin candidates
    #pragma unroll
    for (int l = 0; l < 4; ++l) {
        if ((unsigned int)(comp[l] >> 36) == bin1) {
            unsigned int p = atomicAdd(&s_m, 1u);
            cand[p] = comp[l];
        }
    }
    __syncthreads();
    const unsigned int m = s_m;

    // 5 candidate-only radix passes -> exact GS-th largest composite
    unsigned long long prefix = (unsigned long long)bin1 << 36;
    unsigned long long pmask  = 0xFFull << 36;

    #pragma unroll
    for (int pass = 0; pass < 5; ++pass) {
        const int          shift = (pass < 4) ? (28 - 8 * pass) : 0;
        const unsigned int dmask = (pass < 4) ? 0xFFu : 0xFu;

        if (tid < 256) hist[tid] = 0;
        __syncthreads();
        for (unsigned int idx = tid; idx < m; idx += 1024) {
            unsigned long long k = cand[idx];
            if ((k & pmask) == prefix)
                atomicAdd(&hist[(unsigned int)(k >> shift) & dmask], 1u);
        }
        __syncthreads();
        scan_hist(hist, need, &s_bin, &s_above);
        __syncthreads();
        prefix |= ((unsigned long long)s_bin) << shift;
        pmask  |= ((unsigned long long)dmask) << shift;
        need   -= s_above;
        __syncthreads();
    }
    // Selected set: composite >= prefix (exactly GS keys, unique).

    #pragma unroll
    for (int l = 0; l < 4; ++l) {
        if (comp[l] >= prefix) {
            unsigned int p = atomicAdd(&s_cnt, 1u);
            g_sel[b * GS + p] = comp[l];
        }
    }
}

// ---------------------------------------------------------------------------
// K2 (R8-proven): rank-by-count over 1024 selected keys, 64 CTAs x 128 thr.
// ---------------------------------------------------------------------------
__global__ __launch_bounds__(128) void rank_kernel()
{
    __shared__ unsigned long long sk[GS];  // 8 KB

    const int b   = blockIdx.x >> 3;
    const int c   = blockIdx.x & 7;
    const int tid = threadIdx.x;

    #pragma unroll
    for (int l = 0; l < GS / 128; ++l)
        sk[tid + l * 128] = g_sel[b * GS + tid + l * 128];
    __syncthreads();

    const unsigned long long mine = sk[c * 128 + tid];
    int rank = 0;
    #pragma unroll 8
    for (int j = 0; j < GS; ++j)
        rank += (sk[j] > mine);

    g_idx[b * GS + rank] = (N - 1) - (int)(mine & 0xFFFull);
}

// ---------------------------------------------------------------------------
// K3 (R13-proven): one CTA per output row, 256 threads.
// ---------------------------------------------------------------------------
__global__ __launch_bounds__(256) void gather_kernel(const float* __restrict__ A,
                                                      const float* __restrict__ x,
                                                      float* __restrict__ out)
{
    __shared__ float row[N];        // 16 KB

    const int bi  = blockIdx.x;
    const int b   = bi >> 10;
    const int i   = bi & (GS - 1);
    const int tid = threadIdx.x;

    const int* gi = g_idx + b * GS;
    const int ri  = __ldg(&gi[i]);

    // My four column indices (coalesced, L2-resident)
    const int ci0 = __ldg(&gi[tid]);
    const int ci1 = __ldg(&gi[tid + 256]);
    const int ci2 = __ldg(&gi[tid + 512]);
    const int ci3 = __ldg(&gi[tid + 768]);

    const float4* arow = (const float4*)(A + ((size_t)b * N + ri) * N);
    float4* rowv = (float4*)row;
    rowv[tid]       = __ldcs(&arow[tid]);
    rowv[tid + 256] = __ldcs(&arow[tid + 256]);
    rowv[tid + 512] = __ldcs(&arow[tid + 512]);
    rowv[tid + 768] = __ldcs(&arow[tid + 768]);

    if (tid < F / 4) {
        const float4* xrow = (const float4*)(x + ((size_t)b * N + ri) * F);
        float4* xgrow = (float4*)(out + (size_t)B * GS * GS
                                      + ((size_t)b * GS + i) * F);
        xgrow[tid] = xrow[tid];
    }

    __syncthreads();

    float* orow = out + ((size_t)b * GS + i) * GS;
    orow[tid]       = row[ci0];
    orow[tid + 256] = row[ci1];
    orow[tid + 512] = row[ci2];
    orow[tid + 768] = row[ci3];
}

// ---------------------------------------------------------------------------
extern "C" void kernel_launch(void* const* d_in, const int* in_sizes, int n_in,
                              void* d_out, int out_size)
{
    const float* A = (const float*)d_in[0];  // (8,4096,4096) f32
    const float* x = (const float*)d_in[1];  // (8,4096,128)  f32
    float* out = (float*)d_out;              // At2 (8,1024,1024) ++ xg (8,1024,128)

    select_kernel<<<B, 1024>>>(x);
    rank_kernel<<<B * 8, 128>>>();
    gather_kernel<<<B * GS, 256>>>(A, x, out);
}

// round 17
// speedup vs baseline: 2.2239x; 1.0982x over previous
#include <cuda_runtime.h>
#include <cstdint>

#define B  8
#define N  4096
#define F  128
#define GS 1024

// Scratch (zero-init at module load; g_cnt re-armed every run)
__device__ unsigned int g_keys[B * N];  // monotone-mapped values
__device__ int          g_cnt[B];       // extraction handshake counters
__device__ int          g_idx[B * GS];  // final top-k indices, jax order

__device__ __forceinline__ unsigned int monot(float v) {
    unsigned int u = __float_as_uint(v);
    return (u & 0x80000000u) ? ~u : (u | 0x80000000u); // bigger float -> bigger uint
}

// ---------------------------------------------------------------------------
// scan_hist: warp 0 finds bin containing the `need`-th largest + count above.
// ---------------------------------------------------------------------------
__device__ __forceinline__ void scan_hist(const unsigned int* hist, unsigned int need,
                                          unsigned int* s_bin, unsigned int* s_above)
{
    const int tid = threadIdx.x;
    if (tid < 32) {
        unsigned int sum = 0;
        #pragma unroll
        for (int j = 0; j < 8; ++j) sum += hist[tid * 8 + j];
        unsigned int acc = sum;
        #pragma unroll
        for (int off = 1; off < 32; off <<= 1) {
            unsigned int t = __shfl_down_sync(0xFFFFFFFFu, acc, off);
            if (tid + off < 32) acc += t;
        }
        unsigned int running = acc - sum;      // strictly above my 8-bin group
        #pragma unroll
        for (int j = 7; j >= 0; --j) {
            unsigned int c = hist[tid * 8 + j];
            if (running < need && need <= running + c) {
                *s_bin = (unsigned int)(tid * 8 + j);
                *s_above = running;
            }
            running += c;
        }
    }
}

// ---------------------------------------------------------------------------
// K1: bids 0..B-1 = per-batch select+sort; bids B..B+127 = extractors.
// Extractor k: 256 strided loads of x[:, :, F-1] -> coalesced g_keys writes,
// then bumps g_cnt[batch]. Select CTA b: spins until its 16 extractors done,
// reads keys COALESCED, then hist -> candidate radix -> compact -> bitonic.
// All 136 CTAs co-resident (1 CTA/SM) => spin is deadlock-free.
// composite = (u << 12) | (4095 - i): larger == earlier in jax order; unique.
// ---------------------------------------------------------------------------
__global__ __launch_bounds__(1024) void select_sort_kernel(const float* __restrict__ x)
{
    __shared__ unsigned long long cand[N];      // 32 KB (worst-case threshold bin)
    __shared__ unsigned long long stage[GS];    // 8 KB, selected keys
    __shared__ unsigned int hist[256];
    __shared__ unsigned int s_bin, s_above, s_m, s_cnt;

    const int tid = threadIdx.x;

    // ================= EXTRACTOR CTAs =================
    if (blockIdx.x >= B) {
        const int k = blockIdx.x - B;           // 0..127
        if (tid < 256) {
            const int row = k * 256 + tid;      // global row in (B*N, F) view
            g_keys[row] = monot(__ldcs(&x[(size_t)row * F + (F - 1)]));
        }
        __threadfence();
        __syncthreads();
        if (tid == 0) atomicAdd(&g_cnt[k >> 4], 1);
        return;
    }

    // ================= SELECT CTA (batch b) =================
    const int b = blockIdx.x;

    if (tid == 0) {
        while (atomicAdd(&g_cnt[b], 0) < 16) __nanosleep(64);
        atomicExch(&g_cnt[b], 0);               // re-arm for next replay
    }
    __syncthreads();
    __threadfence();

    if (tid < 256) hist[tid] = 0;
    if (tid == 0) { s_m = 0; s_cnt = 0; }
    __syncthreads();

    // Coalesced key reload (L2-hot), build composites, histogram top-8 bits
    unsigned long long comp[4];
    #pragma unroll
    for (int l = 0; l < 4; ++l) {
        const int i = l * 1024 + tid;
        unsigned int u = g_keys[b * N + i];
        comp[l] = ((unsigned long long)u << 12) | (unsigned int)(N - 1 - i);
    }
    #pragma unroll
    for (int l = 0; l < 4; ++l)
        atomicAdd(&hist[(unsigned int)(comp[l] >> 36)], 1u);
    __syncthreads();

    scan_hist(hist, GS, &s_bin, &s_above);
    __syncthreads();
    const unsigned int bin1 = s_bin;
    unsigned int need = GS - s_above;

    // Compact threshold-bin candidates
    #pragma unroll
    for (int l = 0; l < 4; ++l) {
        if ((unsigned int)(comp[l] >> 36) == bin1) {
            unsigned int p = atomicAdd(&s_m, 1u);
            cand[p] = comp[l];
        }
    }
    __syncthreads();
    const unsigned int m = s_m;

    // 5 candidate-only radix passes -> exact GS-th largest composite
    unsigned long long prefix = (unsigned long long)bin1 << 36;
    unsigned long long pmask  = 0xFFull << 36;

    #pragma unroll
    for (int pass = 0; pass < 5; ++pass) {
        const int          shift = (pass < 4) ? (28 - 8 * pass) : 0;
        const unsigned int dmask = (pass < 4) ? 0xFFu : 0xFu;

        if (tid < 256) hist[tid] = 0;
        __syncthreads();
        for (unsigned int idx = tid; idx < m; idx += 1024) {
            unsigned long long k = cand[idx];
            if ((k & pmask) == prefix)
                atomicAdd(&hist[(unsigned int)(k >> shift) & dmask], 1u);
        }
        __syncthreads();
        scan_hist(hist, need, &s_bin, &s_above);
        __syncthreads();
        prefix |= ((unsigned long long)s_bin) << shift;
        pmask  |= ((unsigned long long)dmask) << shift;
        need   -= s_above;
        __syncthreads();
    }
    // Selected set: composite >= prefix (exactly GS keys, unique).

    #pragma unroll
    for (int l = 0; l < 4; ++l) {
        if (comp[l] >= prefix) {
            unsigned int p = atomicAdd(&s_cnt, 1u);
            stage[p] = comp[l];
        }
    }
    __syncthreads();

    // Bitonic sort DESC. j >= 32 in smem; j < 32 via warp shuffles.
    for (int k = 2; k <= GS; k <<= 1) {
        for (int j = k >> 1; j >= 32; j >>= 1) {
            const int ixj = tid ^ j;
            if (ixj > tid) {
                unsigned long long a = stage[tid];
                unsigned long long c = stage[ixj];
                const bool up = ((tid & k) == 0);
                if ((a < c) == up) { stage[tid] = c; stage[ixj] = a; }
            }
            __syncthreads();
        }
        {
            unsigned long long v = stage[tid];
            const bool up = ((tid & k) == 0);
            const int jmax = (k >> 1 < 16) ? (k >> 1) : 16;
            #pragma unroll
            for (int j = 16; j >= 1; j >>= 1) {
                if (j <= jmax) {
                    unsigned long long p = __shfl_xor_sync(0xFFFFFFFFu, v, j);
                    const bool lower = ((tid & j) == 0);
                    const bool keep_max = (lower == up);
                    v = keep_max ? (v > p ? v : p) : (v < p ? v : p);
                }
            }
            stage[tid] = v;
            __syncthreads();
        }
    }

    g_idx[b * GS + tid] = (N - 1) - (int)(stage[tid] & 0xFFFull);
}

// ---------------------------------------------------------------------------
// K2 (R13-proven, untouched): one CTA per output row, 256 threads.
// ---------------------------------------------------------------------------
__global__ __launch_bounds__(256) void gather_kernel(const float* __restrict__ A,
                                                      const float* __restrict__ x,
                                                      float* __restrict__ out)
{
    __shared__ float row[N];        // 16 KB

    const int bi  = blockIdx.x;
    const int b   = bi >> 10;
    const int i   = bi & (GS - 1);
    const int tid = threadIdx.x;

    const int* gi = g_idx + b * GS;
    const int ri  = __ldg(&gi[i]);

    // My four column indices (coalesced, L2-resident)
    const int ci0 = __ldg(&gi[tid]);
    const int ci1 = __ldg(&gi[tid + 256]);
    const int ci2 = __ldg(&gi[tid + 512]);
    const int ci3 = __ldg(&gi[tid + 768]);

    const float4* arow = (const float4*)(A + ((size_t)b * N + ri) * N);
    float4* rowv = (float4*)row;
    rowv[tid]       = __ldcs(&arow[tid]);
    rowv[tid + 256] = __ldcs(&arow[tid + 256]);
    rowv[tid + 512] = __ldcs(&arow[tid + 512]);
    rowv[tid + 768] = __ldcs(&arow[tid + 768]);

    if (tid < F / 4) {
        const float4* xrow = (const float4*)(x + ((size_t)b * N + ri) * F);
        float4* xgrow = (float4*)(out + (size_t)B * GS * GS
                                      + ((size_t)b * GS + i) * F);
        xgrow[tid] = xrow[tid];
    }

    __syncthreads();

    float* orow = out + ((size_t)b * GS + i) * GS;
    orow[tid]       = row[ci0];
    orow[tid + 256] = row[ci1];
    orow[tid + 512] = row[ci2];
    orow[tid + 768] = row[ci3];
}

// ---------------------------------------------------------------------------
extern "C" void kernel_launch(void* const* d_in, const int* in_sizes, int n_in,
                              void* d_out, int out_size)
{
    const float* A = (const float*)d_in[0];  // (8,4096,4096) f32
    const float* x = (const float*)d_in[1];  // (8,4096,128)  f32
    float* out = (float*)d_out;              // At2 (8,1024,1024) ++ xg (8,1024,128)

    select_sort_kernel<<<B + 128, 1024>>>(x);
    gather_kernel<<<B * GS, 256>>>(A, x, out);
}